// round 6
// baseline (speedup 1.0000x reference)
#include <cuda_runtime.h>
#include <cstdint>

// Problem dims
#define BB 8192
#define HH 1024
#define EE 8

// GEMM tile: 128x256x64, 256 threads, 8 warps (4 M x 2 N), warp tile 32x128
#define BM 128
#define BN 256
#define BK 64
#define NCH (HH / BK)     // 16 chunks
#define NTILE_N (HH / BN) // 4

// per stage: A 128x256B (8192 f) + B 64x1024B (16384 f) = 96KB, 2 stages
#define STAGE_FLOATS 24576
#define SMEM_GEMM_BYTES (2 * STAGE_FLOATS * 4 + BM * 8 + 16)

// ---------------------------------------------------------------------------
// Device scratch (no allocation allowed anywhere)
// ---------------------------------------------------------------------------
__device__ int   g_cnt[EE];
__device__ int   g_tile;
__device__ int   g_tok[EE * BB];            // packed: tok | (slot << 31)
__device__ float g_wt [EE * BB];
__device__ float g_scr[2u * BB * HH];       // 64 MB: per-slot expert outputs
__device__ float g_xc [(size_t)BB * HH];    // 32 MB: tf32-rounded x
__device__ float g_ewc[(size_t)EE * HH * HH]; // 32 MB: tf32-rounded weights

// ---------------------------------------------------------------------------
__device__ __forceinline__ float f2tf32f(float f) {
    uint32_t r;
    asm("cvt.rna.tf32.f32 %0, %1;" : "=r"(r) : "f"(f));
    return __uint_as_float(r);
}

__device__ __forceinline__ void mma_tf32(float* c, const float* a,
                                         float b0, float b1) {
    asm("mma.sync.aligned.m16n8k8.row.col.f32.tf32.tf32.f32 "
        "{%0,%1,%2,%3}, {%4,%5,%6,%7}, {%8,%9}, {%0,%1,%2,%3};"
        : "+f"(c[0]), "+f"(c[1]), "+f"(c[2]), "+f"(c[3])
        : "r"(__float_as_uint(a[0])), "r"(__float_as_uint(a[1])),
          "r"(__float_as_uint(a[2])), "r"(__float_as_uint(a[3])),
          "r"(__float_as_uint(b0)), "r"(__float_as_uint(b1)));
}

__device__ __forceinline__ void cp16(uint32_t dst, const void* src) {
    asm volatile("cp.async.cg.shared.global [%0], [%1], 16;"
                 :: "r"(dst), "l"(src) : "memory");
}
#define CP_COMMIT() asm volatile("cp.async.commit_group;" ::: "memory")
#define CP_WAIT0()  asm volatile("cp.async.wait_group 0;" ::: "memory")

__device__ __forceinline__ uint32_t smem_u32(const void* p) {
    uint32_t a;
    asm("{ .reg .u64 t; cvta.to.shared.u64 t, %1; cvt.u32.u64 %0, t; }"
        : "=r"(a) : "l"(p));
    return a;
}

// ---------------------------------------------------------------------------
// Kernel 0: zero routing counters + tile counter
// ---------------------------------------------------------------------------
__global__ void zero_cnt_kernel() {
    if (threadIdx.x < EE) g_cnt[threadIdx.x] = 0;
    if (threadIdx.x == EE) g_tile = 0;
}

// ---------------------------------------------------------------------------
// Kernel 1: routing — one warp per token. Exact fp32 logits, top-2 with
// first-occurrence tie-break (matches jax.lax.top_k), softmax over the 2.
// Also emits the tf32-rounded copy of x (fused: x is already being read).
// ---------------------------------------------------------------------------
__global__ void __launch_bounds__(256) route_kernel(
    const float* __restrict__ x, const float* __restrict__ gw) {
    int tok = (blockIdx.x * blockDim.x + threadIdx.x) >> 5;
    int lid = threadIdx.x & 31;
    if (tok >= BB) return;

    const float* xr = x + (size_t)tok * HH;
    float*       xc = g_xc + (size_t)tok * HH;
    float acc[EE];
#pragma unroll
    for (int e = 0; e < EE; e++) acc[e] = 0.f;

    for (int i = lid; i < HH; i += 32) {
        float xv = xr[i];
        xc[i] = f2tf32f(xv);
        const float4* g = reinterpret_cast<const float4*>(gw + (size_t)i * EE);
        float4 g0 = g[0], g1 = g[1];
        acc[0] += xv * g0.x; acc[1] += xv * g0.y;
        acc[2] += xv * g0.z; acc[3] += xv * g0.w;
        acc[4] += xv * g1.x; acc[5] += xv * g1.y;
        acc[6] += xv * g1.z; acc[7] += xv * g1.w;
    }
#pragma unroll
    for (int off = 16; off > 0; off >>= 1)
#pragma unroll
        for (int e = 0; e < EE; e++)
            acc[e] += __shfl_xor_sync(0xffffffffu, acc[e], off);

    if (lid == 0) {
        int i0 = 0; float v0 = acc[0];
#pragma unroll
        for (int e = 1; e < EE; e++)
            if (acc[e] > v0) { v0 = acc[e]; i0 = e; }
        int i1 = -1; float v1 = -3.4e38f;
#pragma unroll
        for (int e = 0; e < EE; e++)
            if (e != i0 && acc[e] > v1) { v1 = acc[e]; i1 = e; }
        float ex1 = expf(v1 - v0);
        float inv = 1.0f / (1.0f + ex1);
        int p0 = atomicAdd(&g_cnt[i0], 1);
        g_tok[i0 * BB + p0] = tok;                    // slot 0
        g_wt [i0 * BB + p0] = inv;
        int p1 = atomicAdd(&g_cnt[i1], 1);
        g_tok[i1 * BB + p1] = tok | (int)0x80000000;  // slot 1
        g_wt [i1 * BB + p1] = ex1 * inv;
    }
}

// ---------------------------------------------------------------------------
// Kernel 1b: tf32-round the expert weights (one pass, reused by GEMM)
// ---------------------------------------------------------------------------
__global__ void __launch_bounds__(256) cvt_w_kernel(const float4* __restrict__ src) {
    size_t i = (size_t)blockIdx.x * blockDim.x + threadIdx.x;
    float4 v = src[i];
    float4 o = make_float4(f2tf32f(v.x), f2tf32f(v.y),
                           f2tf32f(v.z), f2tf32f(v.w));
    reinterpret_cast<float4*>(g_ewc)[i] = o;
}

// ---------------------------------------------------------------------------
// Kernel 2: persistent grouped expert GEMM. Work-stealing tile scheduler
// over (expert, m-tile, n-tile); tile 128x256x(K=1024), chunks of BK=64,
// 2-stage cp.async double buffer (one __syncthreads per chunk).
// 8 warps (4Mx2N), warp tile 32x128, mma.sync m16n8k8 tf32.
// XOR-swizzled natural-layout smem (conflict-free LDS.32):
//   A smem: [row 0..127][256B], 16B-granule g -> g ^ (row&7)
//   B smem: [k 0..63][1024B],   granule g -> g ^ ((k&3)<<1)
// Inputs pre-rounded to tf32 (g_xc/g_ewc referenced directly as device
// globals). Epilogue: scale by routing weight, STG to per-slot scratch.
// ---------------------------------------------------------------------------
__global__ void __launch_bounds__(256, 1)
moe_gemm_kernel() {
    const float* __restrict__ xc  = g_xc;
    const float* __restrict__ ewc = g_ewc;

    extern __shared__ float smf[];
    uint32_t sbase = smem_u32(smf);
    int*   s_pack = reinterpret_cast<int*>(smf + 2 * STAGE_FLOATS);
    float* s_w    = reinterpret_cast<float*>(s_pack + BM);
    int*   s_t    = reinterpret_cast<int*>(s_w + BM);

    int tid  = threadIdx.x;
    int lane = tid & 31;
    int w    = tid >> 5;
    int wm   = w >> 1;      // 0..3 (M)
    int wn   = w & 1;       // 0..1 (N)

    // per-expert tile table (identical in every CTA)
    int mt_cnt[EE], pfx[EE + 1];
    pfx[0] = 0;
#pragma unroll
    for (int e = 0; e < EE; e++) {
        mt_cnt[e] = (g_cnt[e] + BM - 1) / BM;
        pfx[e + 1] = pfx[e] + mt_cnt[e] * NTILE_N;
    }
    int total = pfx[EE];

    // consumer fragment constants
    int r = lane >> 2, c = lane & 3;
    int fa0 = wm * 2048 + r * 64 + c;       // A: row*(64f) + within-granule
    int fb0 = c * 256 + (r & 3);            // B: k*(256f) + (n&3)
    int offnt[16];
#pragma unroll
    for (int nt = 0; nt < 16; nt++)
        offnt[nt] = ((wn * 32 + nt * 2 + (r >> 2)) ^ (2 * c)) << 2;

    for (;;) {
        if (tid == 0) *s_t = atomicAdd(&g_tile, 1);
        __syncthreads();                     // broadcast t; close prev epilogue
        int t = *s_t;
        if (t >= total) break;

        // map t -> (e, m0, n0); nt-inner so concurrent tiles share A slab
        int e = 0;
        while (t >= pfx[e + 1]) e++;
        int tl  = t - pfx[e];
        int m0  = (tl >> 2) * BM;
        int n0  = (tl & 3) * BN;
        int cnt = g_cnt[e];
        int rows = min(BM, cnt - m0);

        if (tid < BM) {
            int idx = m0 + tid;
            if (idx < cnt) {
                s_pack[tid] = g_tok[e * BB + idx];
                s_w[tid]    = g_wt [e * BB + idx];
            } else {
                s_pack[tid] = 0;
                s_w[tid]    = 0.f;
            }
        }
        __syncthreads();

        // ---- producer setup ----
        // A: thread covers row = tid>>1, granules g = (tid&1)*8 + p (p 0..7)
        int arow = tid >> 1;
        int ag   = (tid & 1) * 8;
        const float* asrc = xc + (size_t)(s_pack[arow] & 0x7fffffff) * HH
                          + ag * 4;
        uint32_t adst0 = (uint32_t)(arow * 256);
        int arx = arow & 7;
        // B: thread covers k = p*8 + (tid>>5), granules tid&31 and +32
        int bk0 = tid >> 5, gB = tid & 31;
        const float* bsrc = ewc + (size_t)e * HH * HH + (size_t)bk0 * HH
                          + n0 + gB * 4;
        uint32_t bdst0 = (uint32_t)(32768 + bk0 * 1024 +
                                    ((gB ^ ((bk0 & 3) << 1)) << 4));

        auto produce = [&](int kc) {
            uint32_t sb = sbase + (uint32_t)(kc & 1) * (STAGE_FLOATS * 4);
            const float* as = asrc + kc * BK;
#pragma unroll
            for (int p = 0; p < 8; p++)
                cp16(sb + adst0 + (((ag + p) ^ arx) << 4), as + p * 4);
            const float* bs = bsrc + (size_t)kc * BK * HH;
#pragma unroll
            for (int p = 0; p < 8; p++) {
                cp16(sb + bdst0 + p * 8192, bs + (size_t)p * 8 * HH);
                cp16(sb + bdst0 + p * 8192 + 512,
                     bs + (size_t)p * 8 * HH + 128);
            }
            CP_COMMIT();
        };

        float acc[2][16][4];
#pragma unroll
        for (int mt = 0; mt < 2; mt++)
#pragma unroll
            for (int nt = 0; nt < 16; nt++)
#pragma unroll
                for (int q = 0; q < 4; q++) acc[mt][nt][q] = 0.f;

        produce(0);

        for (int kc = 0; kc < NCH; kc++) {
            CP_WAIT0();                      // chunk kc arrived
            __syncthreads();                 // all warps done with other buf
            if (kc + 1 < NCH) produce(kc + 1);

            const float* As = smf + (kc & 1) * STAGE_FLOATS;
            const float* Bs = As + 8192;
#pragma unroll
            for (int s = 0; s < 8; s++) {
                int ax0 = ((2 * s)     ^ r) << 2;
                int ax1 = ((2 * s + 1) ^ r) << 2;
                float a[2][4];
#pragma unroll
                for (int mt = 0; mt < 2; mt++) {
                    a[mt][0] = As[fa0 + mt * 1024 +       ax0];
                    a[mt][1] = As[fa0 + mt * 1024 + 512 + ax0];
                    a[mt][2] = As[fa0 + mt * 1024 +       ax1];
                    a[mt][3] = As[fa0 + mt * 1024 + 512 + ax1];
                }
                const float* Bk = Bs + fb0 + s * 2048;  // +8 k-rows per s
#pragma unroll
                for (int nt = 0; nt < 16; nt++) {
                    float b0 = Bk[offnt[nt]];
                    float b1 = Bk[offnt[nt] + 1024];    // +4 k-rows
                    mma_tf32(acc[0][nt], a[0], b0, b1);
                    mma_tf32(acc[1][nt], a[1], b0, b1);
                }
            }
        }

        // ---- epilogue: scale by routing weight, write per-slot scratch ----
        int cq = c * 2;
#pragma unroll
        for (int mt = 0; mt < 2; mt++) {
#pragma unroll
            for (int rr = 0; rr < 2; rr++) {
                int mloc = wm * 32 + mt * 16 + r + rr * 8;
                if (mloc >= rows) continue;
                int   pack = s_pack[mloc];
                int   slot = ((uint32_t)pack) >> 31;
                int   tk   = pack & 0x7fffffff;
                float wt   = s_w[mloc];
                float* dst = g_scr + ((size_t)slot * BB + tk) * HH
                           + n0 + wn * 128 + cq;
#pragma unroll
                for (int nt = 0; nt < 16; nt++) {
                    float2 v;
                    v.x = wt * acc[mt][nt][rr * 2 + 0];
                    v.y = wt * acc[mt][nt][rr * 2 + 1];
                    *reinterpret_cast<float2*>(dst + nt * 8) = v;
                }
            }
        }
    }
}

// ---------------------------------------------------------------------------
// Kernel 3: combine the two slots -> final output
// ---------------------------------------------------------------------------
__global__ void __launch_bounds__(256) combine_kernel(float4* __restrict__ out) {
    size_t i = (size_t)blockIdx.x * blockDim.x + threadIdx.x;
    const float4* s0 = reinterpret_cast<const float4*>(g_scr);
    const float4* s1 = reinterpret_cast<const float4*>(g_scr + (size_t)BB * HH);
    float4 a = s0[i], b = s1[i];
    out[i] = make_float4(a.x + b.x, a.y + b.y, a.z + b.z, a.w + b.w);
}

// ---------------------------------------------------------------------------
extern "C" void kernel_launch(void* const* d_in, const int* in_sizes, int n_in,
                              void* d_out, int out_size) {
    const float* x  = (const float*)d_in[0];   // [8192, 1024]
    const float* gw = (const float*)d_in[1];   // [1024, 8]
    const float* ew = (const float*)d_in[2];   // [8, 1024, 1024]
    float* out = (float*)d_out;                // [8192, 1024]

    cudaFuncSetAttribute(moe_gemm_kernel,
                         cudaFuncAttributeMaxDynamicSharedMemorySize,
                         SMEM_GEMM_BYTES);

    zero_cnt_kernel<<<1, 32>>>();
    route_kernel<<<BB / 8, 256>>>(x, gw);
    cvt_w_kernel<<<(EE * HH * HH / 4) / 256, 256>>>((const float4*)ew);
    moe_gemm_kernel<<<160, 256, SMEM_GEMM_BYTES>>>();
    combine_kernel<<<(BB * HH / 4) / 256, 256>>>((float4*)out);
}